// round 1
// baseline (speedup 1.0000x reference)
#include <cuda_runtime.h>
#include <math.h>

// Problem constants
#define BATCH 16
#define CCH   256
#define HW    4096            // 64*64
#define CHW   (1048576u)      // 256*4096
// BCHW = 16 * CHW = 16,777,216

// Scratch (no allocation allowed -> __device__ globals)
__device__ float g_y[3ull * 16777216ull];   // [3][B][C][H][W] : fx, gx, hx
__device__ float g_o[16777216ull];          // [B][C][H][W]    : attention output
__device__ float g_wcat[768 * 256];         // concat(wf, wg, wh)
__device__ float g_bcat[768];               // concat(bf, bg, bh)

// ---------------------------------------------------------------------------
// Concatenate the three weight matrices + biases so the f/g/h convs become a
// single 768 x 65536 x 256 GEMM (x is read once).
// ---------------------------------------------------------------------------
__global__ void concat_w_kernel(const float* __restrict__ wf, const float* __restrict__ wg,
                                const float* __restrict__ wh, const float* __restrict__ bf,
                                const float* __restrict__ bg, const float* __restrict__ bh) {
    int i = blockIdx.x * 256 + threadIdx.x;
    if (i < 65536) {
        g_wcat[i]           = wf[i];
        g_wcat[65536 + i]   = wg[i];
        g_wcat[131072 + i]  = wh[i];
    }
    if (i < 256) {
        g_bcat[i]       = bf[i];
        g_bcat[256 + i] = bg[i];
        g_bcat[512 + i] = bh[i];
    }
}

// ---------------------------------------------------------------------------
// Pointwise-conv GEMM:  Y[m, p] = sum_i W[m, i] * X[b, i, p] + bias[m]
//   per batch b (grid.z), M = gridDim.y*128 output channels, N = 4096 pixels.
// Output indexing handles the 3-way concatenated case:
//   Y[((m>>8)*BATCH + b)*CHW + (m&255)*HW + n]
// Classic 128x128x8 tile, 8x8 per thread, float4 smem fragments.
// ---------------------------------------------------------------------------
__global__ __launch_bounds__(256, 2)
void conv_gemm_kernel(const float* __restrict__ X0, const float* __restrict__ W,
                      const float* __restrict__ bias, float* __restrict__ Y) {
    __shared__ float As[8][132];   // [k][m], pad 4 keeps 16B align + kills store conflicts
    __shared__ float Bs[8][128];   // [k][n]

    const int b  = blockIdx.z;
    const int n0 = blockIdx.x * 128;
    const int m0 = blockIdx.y * 128;
    const float* X = X0 + (size_t)b * CHW;

    const int tid = threadIdx.x;
    const int tx  = tid & 15;      // 16 cols of threads
    const int ty  = tid >> 4;      // 16 rows of threads

    float acc[8][8];
#pragma unroll
    for (int i = 0; i < 8; i++)
#pragma unroll
        for (int j = 0; j < 8; j++) acc[i][j] = 0.f;

    for (int k0 = 0; k0 < 256; k0 += 8) {
        // Load A tile transposed: As[k][m] = W[(m0+m)*256 + k0+k]
#pragma unroll
        for (int i = tid; i < 1024; i += 256) {
            int k = i & 7;
            int m = i >> 3;
            As[k][m] = W[(size_t)(m0 + m) * 256 + k0 + k];
        }
        // Load B tile: Bs[k][n] = X[(k0+k)*HW + n0+n]  (fully coalesced)
#pragma unroll
        for (int i = tid; i < 1024; i += 256) {
            int n = i & 127;
            int k = i >> 7;
            Bs[k][n] = X[(size_t)(k0 + k) * HW + n0 + n];
        }
        __syncthreads();

#pragma unroll
        for (int k = 0; k < 8; k++) {
            float a[8], bb[8];
            *(float4*)&a[0]  = *(const float4*)&As[k][ty * 8];
            *(float4*)&a[4]  = *(const float4*)&As[k][ty * 8 + 4];
            *(float4*)&bb[0] = *(const float4*)&Bs[k][tx * 8];
            *(float4*)&bb[4] = *(const float4*)&Bs[k][tx * 8 + 4];
#pragma unroll
            for (int i = 0; i < 8; i++)
#pragma unroll
                for (int j = 0; j < 8; j++) acc[i][j] = fmaf(a[i], bb[j], acc[i][j]);
        }
        __syncthreads();
    }

#pragma unroll
    for (int i = 0; i < 8; i++) {
        int m = m0 + ty * 8 + i;
        float bv = bias[m];
        float* yr = Y + ((size_t)(m >> 8) * BATCH + b) * CHW + (size_t)(m & 255) * HW
                      + n0 + tx * 8;
        float4 v0, v1;
        v0.x = acc[i][0] + bv; v0.y = acc[i][1] + bv;
        v0.z = acc[i][2] + bv; v0.w = acc[i][3] + bv;
        v1.x = acc[i][4] + bv; v1.y = acc[i][5] + bv;
        v1.z = acc[i][6] + bv; v1.w = acc[i][7] + bv;
        *(float4*)yr       = v0;
        *(float4*)(yr + 4) = v1;
    }
}

// ---------------------------------------------------------------------------
// Fused attention, one CTA per (b,c):
//   S = F^T G  (64x64x64)  -> register softmax over rows -> O = Hm @ A
// smem: two 64x65 tiles (33 KB). S/attn live in registers + shuffles.
// ---------------------------------------------------------------------------
__global__ __launch_bounds__(256)
void attn_kernel(const float* __restrict__ y, float* __restrict__ o) {
    const int bc = blockIdx.x;                 // b*256 + c
    const size_t BCHW = (size_t)BATCH * CHW;
    const float* F  = y + (size_t)bc * HW;             // fx[b,c]  [h][w]
    const float* G  = y + BCHW + (size_t)bc * HW;      // gx[b,c]  [h][v]
    const float* Hm = y + 2 * BCHW + (size_t)bc * HW;  // hx[b,c]  [h][w]

    __shared__ float sF[64][65];
    __shared__ float sG[64][65];

    const int tid = threadIdx.x;
    const int tx  = tid & 15;
    const int ty  = tid >> 4;

    for (int i = tid; i < 4096; i += 256) {
        sF[i >> 6][i & 63] = F[i];
        sG[i >> 6][i & 63] = G[i];
    }
    __syncthreads();

    // GEMM1: S[w][v] = sum_h F[h][w] * G[h][v];  thread owns S[ty*4+i][tx*4+j]
    float acc[4][4];
#pragma unroll
    for (int i = 0; i < 4; i++)
#pragma unroll
        for (int j = 0; j < 4; j++) acc[i][j] = 0.f;

    for (int h = 0; h < 64; h++) {
        float a[4], b4[4];
#pragma unroll
        for (int i = 0; i < 4; i++) a[i]  = sF[h][ty * 4 + i];
#pragma unroll
        for (int j = 0; j < 4; j++) b4[j] = sG[h][tx * 4 + j];
#pragma unroll
        for (int i = 0; i < 4; i++)
#pragma unroll
            for (int j = 0; j < 4; j++) acc[i][j] = fmaf(a[i], b4[j], acc[i][j]);
    }

    // Register softmax over v. Row (ty*4+i) is spread across the 16 lanes that
    // share ty -> they are a contiguous 16-lane half-warp: shfl_xor 1,2,4,8.
#pragma unroll
    for (int i = 0; i < 4; i++) {
        float m = fmaxf(fmaxf(acc[i][0], acc[i][1]), fmaxf(acc[i][2], acc[i][3]));
#pragma unroll
        for (int s = 1; s < 16; s <<= 1)
            m = fmaxf(m, __shfl_xor_sync(0xffffffffu, m, s));
        float sum = 0.f;
#pragma unroll
        for (int j = 0; j < 4; j++) {
            acc[i][j] = __expf(acc[i][j] - m);
            sum += acc[i][j];
        }
#pragma unroll
        for (int s = 1; s < 16; s <<= 1)
            sum += __shfl_xor_sync(0xffffffffu, sum, s);
        float inv = 1.0f / sum;
#pragma unroll
        for (int j = 0; j < 4; j++) acc[i][j] *= inv;
    }

    __syncthreads();   // everyone done reading F/G

    // Stage attn into sG, Hm into sF
#pragma unroll
    for (int i = 0; i < 4; i++)
#pragma unroll
        for (int j = 0; j < 4; j++) sG[ty * 4 + i][tx * 4 + j] = acc[i][j];
    for (int i = tid; i < 4096; i += 256) sF[i >> 6][i & 63] = Hm[i];
    __syncthreads();

    // GEMM2: O[h][v] = sum_w Hm[h][w] * A[w][v]
#pragma unroll
    for (int i = 0; i < 4; i++)
#pragma unroll
        for (int j = 0; j < 4; j++) acc[i][j] = 0.f;

    for (int w = 0; w < 64; w++) {
        float a[4], b4[4];
#pragma unroll
        for (int i = 0; i < 4; i++) a[i]  = sF[ty * 4 + i][w];
#pragma unroll
        for (int j = 0; j < 4; j++) b4[j] = sG[w][tx * 4 + j];
#pragma unroll
        for (int i = 0; i < 4; i++)
#pragma unroll
            for (int j = 0; j < 4; j++) acc[i][j] = fmaf(a[i], b4[j], acc[i][j]);
    }

    float* O = o + (size_t)bc * HW;
#pragma unroll
    for (int i = 0; i < 4; i++)
#pragma unroll
        for (int j = 0; j < 4; j++)
            O[(ty * 4 + i) * 64 + tx * 4 + j] = acc[i][j];
}

// ---------------------------------------------------------------------------
extern "C" void kernel_launch(void* const* d_in, const int* in_sizes, int n_in,
                              void* d_out, int out_size) {
    const float* x  = (const float*)d_in[0];
    const float* wf = (const float*)d_in[1];
    const float* bf = (const float*)d_in[2];
    const float* wg = (const float*)d_in[3];
    const float* bg = (const float*)d_in[4];
    const float* wh = (const float*)d_in[5];
    const float* bh = (const float*)d_in[6];
    const float* wv = (const float*)d_in[7];
    const float* bv = (const float*)d_in[8];

    float *yb, *ob, *wcat, *bcat;
    cudaGetSymbolAddress((void**)&yb,   g_y);
    cudaGetSymbolAddress((void**)&ob,   g_o);
    cudaGetSymbolAddress((void**)&wcat, g_wcat);
    cudaGetSymbolAddress((void**)&bcat, g_bcat);

    // 1) concat weights/biases
    concat_w_kernel<<<256, 256>>>(wf, wg, wh, bf, bg, bh);

    // 2) fused f/g/h conv: M=768 (6 m-tiles), N=4096 (32 n-tiles), B=16
    conv_gemm_kernel<<<dim3(32, 6, 16), 256>>>(x, wcat, bcat, yb);

    // 3) per-(b,c) attention: 4096 CTAs
    attn_kernel<<<4096, 256>>>(yb, ob);

    // 4) output conv: M=256 (2 m-tiles)
    conv_gemm_kernel<<<dim3(32, 2, 16), 256>>>(ob, wv, bv, (float*)d_out);
}

// round 3
// speedup vs baseline: 2.2162x; 2.2162x over previous
#include <cuda_runtime.h>
#include <math.h>
#include <stdint.h>

#define BATCH 16
#define HW    4096
#define CHW   1048576u

// Scratch (no allocation allowed -> __device__ globals)
__device__ float g_y[3ull * 16777216ull];   // fx, gx, hx
__device__ float g_o[16777216ull];          // attention output
__device__ float g_wt[256 * 768];           // concat(wf,wg,wh) transposed: [k][m]
__device__ float g_wtv[256 * 256];          // wv transposed: [k][m]
__device__ float g_bcat[768];

__device__ __forceinline__ uint32_t f2tf32(float v) {   // round-to-nearest (unbiased)
    uint32_t r;
    asm("cvt.rna.tf32.f32 %0, %1;" : "=r"(r) : "f"(v));
    return r;
}

__device__ __forceinline__ void mma_tf32(float* c, const uint32_t* a, const uint32_t* b) {
    asm volatile(
        "mma.sync.aligned.m16n8k8.row.col.f32.tf32.tf32.f32 "
        "{%0,%1,%2,%3}, {%4,%5,%6,%7}, {%8,%9}, {%0,%1,%2,%3};"
        : "+f"(c[0]), "+f"(c[1]), "+f"(c[2]), "+f"(c[3])
        : "r"(a[0]), "r"(a[1]), "r"(a[2]), "r"(a[3]), "r"(b[0]), "r"(b[1]));
}

// ---------------------------------------------------------------------------
// Prep: transpose weights to k-major, concat f/g/h, concat biases.
// ---------------------------------------------------------------------------
__global__ void prep_kernel(const float* __restrict__ wf, const float* __restrict__ wg,
                            const float* __restrict__ wh, const float* __restrict__ wv,
                            const float* __restrict__ bf, const float* __restrict__ bg,
                            const float* __restrict__ bh) {
    int idx = blockIdx.x * 256 + threadIdx.x;   // < 196608
    int m = idx >> 8, k = idx & 255;
    const float* w = (m < 256) ? wf : (m < 512) ? wg : wh;
    g_wt[k * 768 + m] = w[(m & 255) * 256 + k];
    if (idx < 65536) g_wtv[k * 256 + m] = wv[idx];   // idx = m*256+k
    if (idx < 256) {
        g_bcat[idx]       = bf[idx];
        g_bcat[256 + idx] = bg[idx];
        g_bcat[512 + idx] = bh[idx];
    }
}

// ---------------------------------------------------------------------------
// HMMA tf32 conv GEMM:  Y[m, n] = sum_k W[m, k] * X[b, k, n] + bias[m]
// WT is k-major [256][wstride]. CTA tile 128x128, k-tile 16, double-buffered.
// 8 warps in 2(m) x 4(n); each warp 64x32 via m16n8k8 tf32.
// Output scatter: Y[((m>>8)*BATCH + b)*CHW + (m&255)*HW + n]  (handles concat).
// ---------------------------------------------------------------------------
#define SSTRIDE 136   // 136 mod 32 == 8 -> frag loads conflict-free

__global__ __launch_bounds__(256, 2)
void conv_hmma_kernel(const float* __restrict__ X0, const float* __restrict__ WT,
                      const float* __restrict__ bias, float* __restrict__ Y,
                      int wstride) {
    extern __shared__ uint32_t dsm[];
    uint32_t (*sA)[16][SSTRIDE] = (uint32_t(*)[16][SSTRIDE])dsm;
    uint32_t (*sB)[16][SSTRIDE] = (uint32_t(*)[16][SSTRIDE])(dsm + 2 * 16 * SSTRIDE);

    const int tid  = threadIdx.x;
    const int lane = tid & 31;
    const int warp = tid >> 5;
    const int mw   = warp >> 2;       // 0..1
    const int nw   = warp & 3;        // 0..3
    const int b    = blockIdx.z;
    const int n0   = blockIdx.x * 128;
    const int m0   = blockIdx.y * 128;
    const float* X = X0 + (size_t)b * CHW;

    // per-thread load coordinates (512 float4 per tile, 2 per thread)
    const int lk  = tid >> 5;          // 0..7   (k row, +8 for second)
    const int lq  = (tid & 31) << 2;   // column quad (m or n)

    float acc[4][4][4];
#pragma unroll
    for (int i = 0; i < 4; i++)
#pragma unroll
        for (int j = 0; j < 4; j++)
#pragma unroll
            for (int r = 0; r < 4; r++) acc[i][j][r] = 0.f;

    // prologue: load k-tile 0 directly
    {
#pragma unroll
        for (int h = 0; h < 2; h++) {
            int k = lk + h * 8;
            float4 a = *(const float4*)&WT[(size_t)k * wstride + m0 + lq];
            float4 x = *(const float4*)&X[(size_t)k * HW + n0 + lq];
            uint32_t* pa = &sA[0][k][lq];
            uint32_t* pb = &sB[0][k][lq];
            pa[0] = f2tf32(a.x); pa[1] = f2tf32(a.y); pa[2] = f2tf32(a.z); pa[3] = f2tf32(a.w);
            pb[0] = f2tf32(x.x); pb[1] = f2tf32(x.y); pb[2] = f2tf32(x.z); pb[3] = f2tf32(x.w);
        }
    }
    __syncthreads();

    for (int kt = 0; kt < 16; kt++) {
        const int cur = kt & 1, nxt = cur ^ 1;

        // stage next tile's global data into registers (overlaps with HMMA below)
        float4 na[2], nb[2];
        if (kt < 15) {
            int k0 = (kt + 1) * 16;
#pragma unroll
            for (int h = 0; h < 2; h++) {
                int k = k0 + lk + h * 8;
                na[h] = *(const float4*)&WT[(size_t)k * wstride + m0 + lq];
                nb[h] = *(const float4*)&X[(size_t)k * HW + n0 + lq];
            }
        }

        // compute on cur
#pragma unroll
        for (int kk = 0; kk < 16; kk += 8) {
            uint32_t af[4][4];
#pragma unroll
            for (int mi = 0; mi < 4; mi++) {
                int mrow = mw * 64 + mi * 16 + (lane >> 2);
                af[mi][0] = sA[cur][kk + (lane & 3)][mrow];
                af[mi][1] = sA[cur][kk + (lane & 3)][mrow + 8];
                af[mi][2] = sA[cur][kk + (lane & 3) + 4][mrow];
                af[mi][3] = sA[cur][kk + (lane & 3) + 4][mrow + 8];
            }
            uint32_t bfr[4][2];
#pragma unroll
            for (int nj = 0; nj < 4; nj++) {
                int ncol = nw * 32 + nj * 8 + (lane >> 2);
                bfr[nj][0] = sB[cur][kk + (lane & 3)][ncol];
                bfr[nj][1] = sB[cur][kk + (lane & 3) + 4][ncol];
            }
#pragma unroll
            for (int mi = 0; mi < 4; mi++)
#pragma unroll
                for (int nj = 0; nj < 4; nj++)
                    mma_tf32(acc[mi][nj], af[mi], bfr[nj]);
        }

        if (kt < 15) {
#pragma unroll
            for (int h = 0; h < 2; h++) {
                int k = lk + h * 8;
                uint32_t* pa = &sA[nxt][k][lq];
                uint32_t* pb = &sB[nxt][k][lq];
                pa[0] = f2tf32(na[h].x); pa[1] = f2tf32(na[h].y);
                pa[2] = f2tf32(na[h].z); pa[3] = f2tf32(na[h].w);
                pb[0] = f2tf32(nb[h].x); pb[1] = f2tf32(nb[h].y);
                pb[2] = f2tf32(nb[h].z); pb[3] = f2tf32(nb[h].w);
            }
        }
        __syncthreads();
    }

    // epilogue: bias + v2 stores in accumulator layout
#pragma unroll
    for (int mi = 0; mi < 4; mi++) {
        int mr0 = m0 + mw * 64 + mi * 16 + (lane >> 2);
        float bv0 = bias[mr0];
        float bv1 = bias[mr0 + 8];
        float* y0 = Y + ((size_t)(mr0 >> 8) * BATCH + b) * CHW + (size_t)(mr0 & 255) * HW + n0;
        int mr1 = mr0 + 8;
        float* y1 = Y + ((size_t)(mr1 >> 8) * BATCH + b) * CHW + (size_t)(mr1 & 255) * HW + n0;
#pragma unroll
        for (int nj = 0; nj < 4; nj++) {
            int nc = nw * 32 + nj * 8 + 2 * (lane & 3);
            float2 v0 = make_float2(acc[mi][nj][0] + bv0, acc[mi][nj][1] + bv0);
            float2 v1 = make_float2(acc[mi][nj][2] + bv1, acc[mi][nj][3] + bv1);
            *(float2*)(y0 + nc) = v0;
            *(float2*)(y1 + nc) = v1;
        }
    }
}

// ---------------------------------------------------------------------------
// Fused attention, one CTA per (b,c): S = F^T G -> softmax -> O = Hm @ A
// ---------------------------------------------------------------------------
__global__ __launch_bounds__(256)
void attn_kernel(const float* __restrict__ y, float* __restrict__ o) {
    const int bc = blockIdx.x;
    const size_t BCHW = (size_t)BATCH * CHW;
    const float* F  = y + (size_t)bc * HW;
    const float* G  = y + BCHW + (size_t)bc * HW;
    const float* Hm = y + 2 * BCHW + (size_t)bc * HW;

    __shared__ float sF[64][65];
    __shared__ float sG[64][65];

    const int tid = threadIdx.x;
    const int tx  = tid & 15;
    const int ty  = tid >> 4;

    for (int i = tid; i < 4096; i += 256) {
        sF[i >> 6][i & 63] = F[i];
        sG[i >> 6][i & 63] = G[i];
    }
    __syncthreads();

    float acc[4][4];
#pragma unroll
    for (int i = 0; i < 4; i++)
#pragma unroll
        for (int j = 0; j < 4; j++) acc[i][j] = 0.f;

    for (int h = 0; h < 64; h++) {
        float a[4], b4[4];
#pragma unroll
        for (int i = 0; i < 4; i++) a[i]  = sF[h][ty * 4 + i];
#pragma unroll
        for (int j = 0; j < 4; j++) b4[j] = sG[h][tx * 4 + j];
#pragma unroll
        for (int i = 0; i < 4; i++)
#pragma unroll
            for (int j = 0; j < 4; j++) acc[i][j] = fmaf(a[i], b4[j], acc[i][j]);
    }

#pragma unroll
    for (int i = 0; i < 4; i++) {
        float m = fmaxf(fmaxf(acc[i][0], acc[i][1]), fmaxf(acc[i][2], acc[i][3]));
#pragma unroll
        for (int s = 1; s < 16; s <<= 1)
            m = fmaxf(m, __shfl_xor_sync(0xffffffffu, m, s));
        float sum = 0.f;
#pragma unroll
        for (int j = 0; j < 4; j++) {
            acc[i][j] = __expf(acc[i][j] - m);
            sum += acc[i][j];
        }
#pragma unroll
        for (int s = 1; s < 16; s <<= 1)
            sum += __shfl_xor_sync(0xffffffffu, sum, s);
        float inv = 1.0f / sum;
#pragma unroll
        for (int j = 0; j < 4; j++) acc[i][j] *= inv;
    }

    __syncthreads();

#pragma unroll
    for (int i = 0; i < 4; i++)
#pragma unroll
        for (int j = 0; j < 4; j++) sG[ty * 4 + i][tx * 4 + j] = acc[i][j];
    for (int i = tid; i < 4096; i += 256) sF[i >> 6][i & 63] = Hm[i];
    __syncthreads();

#pragma unroll
    for (int i = 0; i < 4; i++)
#pragma unroll
        for (int j = 0; j < 4; j++) acc[i][j] = 0.f;

    for (int w = 0; w < 64; w++) {
        float a[4], b4[4];
#pragma unroll
        for (int i = 0; i < 4; i++) a[i]  = sF[ty * 4 + i][w];
#pragma unroll
        for (int j = 0; j < 4; j++) b4[j] = sG[w][tx * 4 + j];
#pragma unroll
        for (int i = 0; i < 4; i++)
#pragma unroll
            for (int j = 0; j < 4; j++) acc[i][j] = fmaf(a[i], b4[j], acc[i][j]);
    }

    float* O = o + (size_t)bc * HW;
#pragma unroll
    for (int i = 0; i < 4; i++)
#pragma unroll
        for (int j = 0; j < 4; j++)
            O[(ty * 4 + i) * 64 + tx * 4 + j] = acc[i][j];
}

// ---------------------------------------------------------------------------
extern "C" void kernel_launch(void* const* d_in, const int* in_sizes, int n_in,
                              void* d_out, int out_size) {
    const float* x  = (const float*)d_in[0];
    const float* wf = (const float*)d_in[1];
    const float* bf = (const float*)d_in[2];
    const float* wg = (const float*)d_in[3];
    const float* bg = (const float*)d_in[4];
    const float* wh = (const float*)d_in[5];
    const float* bh = (const float*)d_in[6];
    const float* wv = (const float*)d_in[7];
    const float* bv = (const float*)d_in[8];

    float *yb, *ob, *wt, *wtv, *bcat;
    cudaGetSymbolAddress((void**)&yb,   g_y);
    cudaGetSymbolAddress((void**)&ob,   g_o);
    cudaGetSymbolAddress((void**)&wt,   g_wt);
    cudaGetSymbolAddress((void**)&wtv,  g_wtv);
    cudaGetSymbolAddress((void**)&bcat, g_bcat);

    const int CONV_SMEM = 2 * 2 * 16 * SSTRIDE * 4;   // 69632
    static int attr_set = 0;
    cudaFuncSetAttribute(conv_hmma_kernel,
                         cudaFuncAttributeMaxDynamicSharedMemorySize, CONV_SMEM);
    (void)attr_set;

    // 1) transpose + concat weights/biases
    prep_kernel<<<768, 256>>>(wf, wg, wh, wv, bf, bg, bh);

    // 2) fused f/g/h conv: M=768 (6 tiles), N=4096 (32 tiles), B=16
    conv_hmma_kernel<<<dim3(32, 6, 16), 256, CONV_SMEM>>>(x, wt, bcat, yb, 768);

    // 3) per-(b,c) attention
    attn_kernel<<<4096, 256>>>(yb, ob);

    // 4) output conv: M=256 (2 tiles)
    conv_hmma_kernel<<<dim3(32, 2, 16), 256, CONV_SMEM>>>(ob, wtv, bv, (float*)d_out, 256);
}

// round 4
// speedup vs baseline: 2.7563x; 1.2437x over previous
#include <cuda_runtime.h>
#include <math.h>
#include <stdint.h>

#define BATCH 16
#define HW    4096
#define CHW   1048576u

// Scratch (no allocation allowed -> __device__ globals)
__device__ float g_y[3ull * 16777216ull];   // fx, gx, hx
__device__ float g_o[16777216ull];          // attention output (tf32-rounded)
__device__ float g_xr[16777216ull];         // x, tf32-rounded
__device__ float g_wt[256 * 768];           // concat(wf,wg,wh) transposed [k][m], tf32-rounded
__device__ float g_wtv[256 * 256];          // wv transposed [k][m], tf32-rounded
__device__ float g_bcat[768];

__device__ __forceinline__ uint32_t f2tf32(float v) {   // round-to-nearest (unbiased)
    uint32_t r;
    asm("cvt.rna.tf32.f32 %0, %1;" : "=r"(r) : "f"(v));
    return r;
}
__device__ __forceinline__ float rtf(float v) { return __uint_as_float(f2tf32(v)); }

__device__ __forceinline__ void mma_tf32(float* c, const uint32_t* a, const uint32_t* b) {
    asm volatile(
        "mma.sync.aligned.m16n8k8.row.col.f32.tf32.tf32.f32 "
        "{%0,%1,%2,%3}, {%4,%5,%6,%7}, {%8,%9}, {%0,%1,%2,%3};"
        : "+f"(c[0]), "+f"(c[1]), "+f"(c[2]), "+f"(c[3])
        : "r"(a[0]), "r"(a[1]), "r"(a[2]), "r"(a[3]), "r"(b[0]), "r"(b[1]));
}

__device__ __forceinline__ void cpa16(uint32_t s, const void* g) {
    asm volatile("cp.async.cg.shared.global [%0], [%1], 16;" :: "r"(s), "l"(g));
}
#define CP_COMMIT()  asm volatile("cp.async.commit_group;" ::: "memory")
#define CP_WAIT2()   asm volatile("cp.async.wait_group 2;" ::: "memory")

// ---------------------------------------------------------------------------
// Prep: transpose weights to k-major + tf32-round, concat f/g/h, concat biases.
// ---------------------------------------------------------------------------
__global__ void prep_kernel(const float* __restrict__ wf, const float* __restrict__ wg,
                            const float* __restrict__ wh, const float* __restrict__ wv,
                            const float* __restrict__ bf, const float* __restrict__ bg,
                            const float* __restrict__ bh) {
    int idx = blockIdx.x * 256 + threadIdx.x;   // < 196608
    int m = idx >> 8, k = idx & 255;
    const float* w = (m < 256) ? wf : (m < 512) ? wg : wh;
    g_wt[k * 768 + m] = rtf(w[(m & 255) * 256 + k]);
    if (idx < 65536) g_wtv[k * 256 + m] = rtf(wv[idx]);   // idx = m*256+k
    if (idx < 256) {
        g_bcat[idx]       = bf[idx];
        g_bcat[256 + idx] = bg[idx];
        g_bcat[512 + idx] = bh[idx];
    }
}

// Round x to tf32 once (so the conv B-tiles can be cp.async'd without cvt).
__global__ void round_x_kernel(const float* __restrict__ x) {
    size_t i = ((size_t)blockIdx.x * 256 + threadIdx.x) * 4;
    float4 v = *(const float4*)&x[i];
    v.x = rtf(v.x); v.y = rtf(v.y); v.z = rtf(v.z); v.w = rtf(v.w);
    *(float4*)&g_xr[i] = v;
}

// ---------------------------------------------------------------------------
// HMMA tf32 conv GEMM:  Y[m, n] = sum_k W[m, k] * X[b, k, n] + bias[m]
// WT k-major [256][wstride], inputs pre-rounded to tf32.
// CTA tile 128x128, k-tile 16, 4-stage cp.async pipeline.
// 8 warps in 2(m) x 4(n); each warp 64x32 via m16n8k8 tf32.
// Output scatter: Y[((m>>8)*BATCH + b)*CHW + (m&255)*HW + n]  (handles concat).
// ---------------------------------------------------------------------------
#define SSTRIDE 136   // 136 mod 32 == 8 -> frag loads conflict-free
#define SA_OFF(buf, k) ((((buf) * 2 + 0) * 16 + (k)) * SSTRIDE)
#define SB_OFF(buf, k) ((((buf) * 2 + 1) * 16 + (k)) * SSTRIDE)
#define CONV_SMEM (4 * 2 * 16 * SSTRIDE * 4)   // 69632

__global__ __launch_bounds__(256, 2)
void conv_hmma_kernel(const float* __restrict__ X0, const float* __restrict__ WT,
                      const float* __restrict__ bias, float* __restrict__ Y,
                      int wstride) {
    extern __shared__ uint32_t dsm[];

    const int tid  = threadIdx.x;
    const int lane = tid & 31;
    const int warp = tid >> 5;
    const int mw   = warp >> 2;       // 0..1
    const int nw   = warp & 3;        // 0..3
    const int b    = blockIdx.z;
    const int n0   = blockIdx.x * 128;
    const int m0   = blockIdx.y * 128;
    const float* X = X0 + (size_t)b * CHW;

    // loader coordinates: thread covers rows {tid>>5, tid>>5 + 8}, 16B col chunk
    const int lrow = tid >> 5;            // 0..7
    const int lcol = (tid & 31) << 2;     // 0..124
    const float* gA = WT + (size_t)lrow * wstride + m0 + lcol;
    const float* gB = X  + (size_t)lrow * HW + n0 + lcol;
    const uint32_t sbase = (uint32_t)__cvta_generic_to_shared(dsm);

    float acc[4][4][4];
#pragma unroll
    for (int i = 0; i < 4; i++)
#pragma unroll
        for (int j = 0; j < 4; j++)
#pragma unroll
            for (int r = 0; r < 4; r++) acc[i][j][r] = 0.f;

    // prologue: stages 0..2
#pragma unroll
    for (int s = 0; s < 3; s++) {
        const int buf = s;
#pragma unroll
        for (int h = 0; h < 2; h++) {
            cpa16(sbase + (SA_OFF(buf, lrow + h * 8) + lcol) * 4,
                  gA + (size_t)(s * 16 + h * 8) * wstride);
            cpa16(sbase + (SB_OFF(buf, lrow + h * 8) + lcol) * 4,
                  gB + (size_t)(s * 16 + h * 8) * HW);
        }
        CP_COMMIT();
    }

    for (int kt = 0; kt < 16; kt++) {
        const int buf = kt & 3;
        CP_WAIT2();
        __syncthreads();

        // issue stage kt+3 (its buffer's compute finished at iteration kt-1)
        if (kt < 13) {
            const int s = kt + 3, nb = s & 3;
#pragma unroll
            for (int h = 0; h < 2; h++) {
                cpa16(sbase + (SA_OFF(nb, lrow + h * 8) + lcol) * 4,
                      gA + (size_t)(s * 16 + h * 8) * wstride);
                cpa16(sbase + (SB_OFF(nb, lrow + h * 8) + lcol) * 4,
                      gB + (size_t)(s * 16 + h * 8) * HW);
            }
        }
        CP_COMMIT();

        // compute on buf
        const uint32_t* A0 = dsm + SA_OFF(buf, 0) + (lane & 3) * SSTRIDE
                                 + mw * 64 + (lane >> 2);
        const uint32_t* B0 = dsm + SB_OFF(buf, 0) + (lane & 3) * SSTRIDE
                                 + nw * 32 + (lane >> 2);
#pragma unroll
        for (int kk = 0; kk < 16; kk += 8) {
            const uint32_t* Ak = A0 + kk * SSTRIDE;
            const uint32_t* Bk = B0 + kk * SSTRIDE;
            uint32_t af[4][4];
#pragma unroll
            for (int mi = 0; mi < 4; mi++) {
                af[mi][0] = Ak[mi * 16];
                af[mi][1] = Ak[mi * 16 + 8];
                af[mi][2] = Ak[4 * SSTRIDE + mi * 16];
                af[mi][3] = Ak[4 * SSTRIDE + mi * 16 + 8];
            }
            uint32_t bfr[4][2];
#pragma unroll
            for (int nj = 0; nj < 4; nj++) {
                bfr[nj][0] = Bk[nj * 8];
                bfr[nj][1] = Bk[4 * SSTRIDE + nj * 8];
            }
#pragma unroll
            for (int mi = 0; mi < 4; mi++)
#pragma unroll
                for (int nj = 0; nj < 4; nj++)
                    mma_tf32(acc[mi][nj], af[mi], bfr[nj]);
        }
        __syncthreads();
    }

    // epilogue: bias + v2 stores in accumulator layout
#pragma unroll
    for (int mi = 0; mi < 4; mi++) {
        int mr0 = m0 + mw * 64 + mi * 16 + (lane >> 2);
        float bv0 = bias[mr0];
        float bv1 = bias[mr0 + 8];
        float* y0 = Y + ((size_t)(mr0 >> 8) * BATCH + b) * CHW + (size_t)(mr0 & 255) * HW + n0;
        int mr1 = mr0 + 8;
        float* y1 = Y + ((size_t)(mr1 >> 8) * BATCH + b) * CHW + (size_t)(mr1 & 255) * HW + n0;
#pragma unroll
        for (int nj = 0; nj < 4; nj++) {
            int nc = nw * 32 + nj * 8 + 2 * (lane & 3);
            float2 v0 = make_float2(acc[mi][nj][0] + bv0, acc[mi][nj][1] + bv0);
            float2 v1 = make_float2(acc[mi][nj][2] + bv1, acc[mi][nj][3] + bv1);
            *(float2*)(y0 + nc) = v0;
            *(float2*)(y1 + nc) = v1;
        }
    }
}

// ---------------------------------------------------------------------------
// Fused attention, one CTA per (b,c): S = F^T G -> softmax -> O = Hm @ A
// Padded smem (stride 68 -> 16B-aligned rows) so fragment loads are LDS.128.
// Output written tf32-rounded so the final conv needs no conversion.
// ---------------------------------------------------------------------------
__global__ __launch_bounds__(256)
void attn_kernel(const float* __restrict__ y, float* __restrict__ o) {
    const int bc = blockIdx.x;
    const size_t BCHW = (size_t)BATCH * CHW;
    const float* F  = y + (size_t)bc * HW;
    const float* G  = y + BCHW + (size_t)bc * HW;
    const float* Hm = y + 2 * BCHW + (size_t)bc * HW;

    __shared__ __align__(16) float sF[64][68];
    __shared__ __align__(16) float sG[64][68];

    const int tid = threadIdx.x;
    const int tx  = tid & 15;
    const int ty  = tid >> 4;

    for (int i = tid * 4; i < 4096; i += 1024) {
        *(float4*)&sF[i >> 6][i & 63] = *(const float4*)&F[i];
        *(float4*)&sG[i >> 6][i & 63] = *(const float4*)&G[i];
    }
    __syncthreads();

    float acc[4][4];
#pragma unroll
    for (int i = 0; i < 4; i++)
#pragma unroll
        for (int j = 0; j < 4; j++) acc[i][j] = 0.f;

#pragma unroll 4
    for (int h = 0; h < 64; h++) {
        float4 a4 = *(const float4*)&sF[h][ty * 4];
        float4 b4 = *(const float4*)&sG[h][tx * 4];
        float a[4] = {a4.x, a4.y, a4.z, a4.w};
        float bb[4] = {b4.x, b4.y, b4.z, b4.w};
#pragma unroll
        for (int i = 0; i < 4; i++)
#pragma unroll
            for (int j = 0; j < 4; j++) acc[i][j] = fmaf(a[i], bb[j], acc[i][j]);
    }

#pragma unroll
    for (int i = 0; i < 4; i++) {
        float m = fmaxf(fmaxf(acc[i][0], acc[i][1]), fmaxf(acc[i][2], acc[i][3]));
#pragma unroll
        for (int s = 1; s < 16; s <<= 1)
            m = fmaxf(m, __shfl_xor_sync(0xffffffffu, m, s));
        float sum = 0.f;
#pragma unroll
        for (int j = 0; j < 4; j++) {
            acc[i][j] = __expf(acc[i][j] - m);
            sum += acc[i][j];
        }
#pragma unroll
        for (int s = 1; s < 16; s <<= 1)
            sum += __shfl_xor_sync(0xffffffffu, sum, s);
        float inv = 1.0f / sum;
#pragma unroll
        for (int j = 0; j < 4; j++) acc[i][j] *= inv;
    }

    __syncthreads();

#pragma unroll
    for (int i = 0; i < 4; i++)
#pragma unroll
        for (int j = 0; j < 4; j++) sG[ty * 4 + i][tx * 4 + j] = acc[i][j];
    for (int i = tid * 4; i < 4096; i += 1024)
        *(float4*)&sF[i >> 6][i & 63] = *(const float4*)&Hm[i];
    __syncthreads();

#pragma unroll
    for (int i = 0; i < 4; i++)
#pragma unroll
        for (int j = 0; j < 4; j++) acc[i][j] = 0.f;

#pragma unroll 4
    for (int w = 0; w < 64; w++) {
        float a[4];
#pragma unroll
        for (int i = 0; i < 4; i++) a[i] = sF[ty * 4 + i][w];   // broadcast LDS
        float4 b4 = *(const float4*)&sG[w][tx * 4];
        float bb[4] = {b4.x, b4.y, b4.z, b4.w};
#pragma unroll
        for (int i = 0; i < 4; i++)
#pragma unroll
            for (int j = 0; j < 4; j++) acc[i][j] = fmaf(a[i], bb[j], acc[i][j]);
    }

    float* O = o + (size_t)bc * HW;
#pragma unroll
    for (int i = 0; i < 4; i++) {
        float4 v;
        v.x = rtf(acc[i][0]); v.y = rtf(acc[i][1]);
        v.z = rtf(acc[i][2]); v.w = rtf(acc[i][3]);
        *(float4*)&O[(ty * 4 + i) * 64 + tx * 4] = v;
    }
}

// ---------------------------------------------------------------------------
extern "C" void kernel_launch(void* const* d_in, const int* in_sizes, int n_in,
                              void* d_out, int out_size) {
    const float* x  = (const float*)d_in[0];
    const float* wf = (const float*)d_in[1];
    const float* bf = (const float*)d_in[2];
    const float* wg = (const float*)d_in[3];
    const float* bg = (const float*)d_in[4];
    const float* wh = (const float*)d_in[5];
    const float* bh = (const float*)d_in[6];
    const float* wv = (const float*)d_in[7];
    const float* bv = (const float*)d_in[8];

    float *yb, *ob, *xr, *wt, *wtv, *bcat;
    cudaGetSymbolAddress((void**)&yb,   g_y);
    cudaGetSymbolAddress((void**)&ob,   g_o);
    cudaGetSymbolAddress((void**)&xr,   g_xr);
    cudaGetSymbolAddress((void**)&wt,   g_wt);
    cudaGetSymbolAddress((void**)&wtv,  g_wtv);
    cudaGetSymbolAddress((void**)&bcat, g_bcat);

    cudaFuncSetAttribute(conv_hmma_kernel,
                         cudaFuncAttributeMaxDynamicSharedMemorySize, CONV_SMEM);

    // 1) weight transpose + rounding; x rounding
    prep_kernel<<<768, 256>>>(wf, wg, wh, wv, bf, bg, bh);
    round_x_kernel<<<16384, 256>>>(x);

    // 2) fused f/g/h conv: M=768 (6 tiles), N=4096 (32 tiles), B=16
    conv_hmma_kernel<<<dim3(32, 6, 16), 256, CONV_SMEM>>>(xr, wt, bcat, yb, 768);

    // 3) per-(b,c) attention
    attn_kernel<<<4096, 256>>>(yb, ob);

    // 4) output conv: M=256 (2 tiles)
    conv_hmma_kernel<<<dim3(32, 2, 16), 256, CONV_SMEM>>>(ob, wtv, bv, (float*)d_out, 256);
}

// round 5
// speedup vs baseline: 2.9243x; 1.0609x over previous
#include <cuda_runtime.h>
#include <math.h>
#include <stdint.h>

#define BATCH 16
#define HW    4096
#define CHW   1048576u

// Scratch (no allocation allowed -> __device__ globals)
__device__ float g_y[3ull * 16777216ull];   // fx, gx, hx
__device__ float g_o[16777216ull];          // attention output (tf32-rounded)
__device__ float g_xr[16777216ull];         // x, tf32-rounded
__device__ float g_wt[256 * 768];           // concat(wf,wg,wh) transposed [k][m], tf32-rounded
__device__ float g_wtv[256 * 256];          // wv transposed [k][m], tf32-rounded
__device__ float g_bcat[768];

__device__ __forceinline__ uint32_t f2tf32(float v) {   // round-to-nearest (unbiased)
    uint32_t r;
    asm("cvt.rna.tf32.f32 %0, %1;" : "=r"(r) : "f"(v));
    return r;
}
__device__ __forceinline__ float rtf(float v) { return __uint_as_float(f2tf32(v)); }

__device__ __forceinline__ void mma_tf32(float* c, const uint32_t* a, const uint32_t* b) {
    asm volatile(
        "mma.sync.aligned.m16n8k8.row.col.f32.tf32.tf32.f32 "
        "{%0,%1,%2,%3}, {%4,%5,%6,%7}, {%8,%9}, {%0,%1,%2,%3};"
        : "+f"(c[0]), "+f"(c[1]), "+f"(c[2]), "+f"(c[3])
        : "r"(a[0]), "r"(a[1]), "r"(a[2]), "r"(a[3]), "r"(b[0]), "r"(b[1]));
}

__device__ __forceinline__ void cpa16(uint32_t s, const void* g) {
    asm volatile("cp.async.cg.shared.global [%0], [%1], 16;" :: "r"(s), "l"(g));
}
#define CP_COMMIT()  asm volatile("cp.async.commit_group;" ::: "memory")
#define CP_WAIT2()   asm volatile("cp.async.wait_group 2;" ::: "memory")

// ---------------------------------------------------------------------------
// Prep: transpose weights to k-major + tf32-round, concat f/g/h, concat biases.
// ---------------------------------------------------------------------------
__global__ void prep_kernel(const float* __restrict__ wf, const float* __restrict__ wg,
                            const float* __restrict__ wh, const float* __restrict__ wv,
                            const float* __restrict__ bf, const float* __restrict__ bg,
                            const float* __restrict__ bh) {
    int idx = blockIdx.x * 256 + threadIdx.x;   // < 196608
    int m = idx >> 8, k = idx & 255;
    const float* w = (m < 256) ? wf : (m < 512) ? wg : wh;
    g_wt[k * 768 + m] = rtf(w[(m & 255) * 256 + k]);
    if (idx < 65536) g_wtv[k * 256 + m] = rtf(wv[idx]);   // idx = m*256+k
    if (idx < 256) {
        g_bcat[idx]       = bf[idx];
        g_bcat[256 + idx] = bg[idx];
        g_bcat[512 + idx] = bh[idx];
    }
}

// Round x to tf32 once (so the conv B-tiles can be cp.async'd without cvt).
__global__ void round_x_kernel(const float* __restrict__ x) {
    size_t i = ((size_t)blockIdx.x * 256 + threadIdx.x) * 4;
    float4 v = *(const float4*)&x[i];
    v.x = rtf(v.x); v.y = rtf(v.y); v.z = rtf(v.z); v.w = rtf(v.w);
    *(float4*)&g_xr[i] = v;
}

// ---------------------------------------------------------------------------
// HMMA tf32 conv GEMM:  Y[m, n] = sum_k W[m, k] * X[b, k, n] + bias[m]
// WT k-major [256][wstride], inputs pre-rounded to tf32.
// CTA tile 128x128, k-tile 16, 4-stage cp.async pipeline.
// 8 warps in 2(m) x 4(n); each warp 64x32 via m16n8k8 tf32.
// Output scatter: Y[((m>>8)*BATCH + b)*CHW + (m&255)*HW + n]  (handles concat).
// ---------------------------------------------------------------------------
#define SSTRIDE 136   // 136 mod 32 == 8 -> frag loads conflict-free
#define SA_OFF(buf, k) ((((buf) * 2 + 0) * 16 + (k)) * SSTRIDE)
#define SB_OFF(buf, k) ((((buf) * 2 + 1) * 16 + (k)) * SSTRIDE)
#define CONV_SMEM (4 * 2 * 16 * SSTRIDE * 4)   // 69632

__global__ __launch_bounds__(256, 2)
void conv_hmma_kernel(const float* __restrict__ X0, const float* __restrict__ WT,
                      const float* __restrict__ bias, float* __restrict__ Y,
                      int wstride) {
    extern __shared__ uint32_t dsm[];

    const int tid  = threadIdx.x;
    const int lane = tid & 31;
    const int warp = tid >> 5;
    const int mw   = warp >> 2;       // 0..1
    const int nw   = warp & 3;        // 0..3
    const int b    = blockIdx.z;
    const int n0   = blockIdx.x * 128;
    const int m0   = blockIdx.y * 128;
    const float* X = X0 + (size_t)b * CHW;

    const int lrow = tid >> 5;            // 0..7
    const int lcol = (tid & 31) << 2;     // 0..124
    const float* gA = WT + (size_t)lrow * wstride + m0 + lcol;
    const float* gB = X  + (size_t)lrow * HW + n0 + lcol;
    const uint32_t sbase = (uint32_t)__cvta_generic_to_shared(dsm);

    float acc[4][4][4];
#pragma unroll
    for (int i = 0; i < 4; i++)
#pragma unroll
        for (int j = 0; j < 4; j++)
#pragma unroll
            for (int r = 0; r < 4; r++) acc[i][j][r] = 0.f;

#pragma unroll
    for (int s = 0; s < 3; s++) {
        const int buf = s;
#pragma unroll
        for (int h = 0; h < 2; h++) {
            cpa16(sbase + (SA_OFF(buf, lrow + h * 8) + lcol) * 4,
                  gA + (size_t)(s * 16 + h * 8) * wstride);
            cpa16(sbase + (SB_OFF(buf, lrow + h * 8) + lcol) * 4,
                  gB + (size_t)(s * 16 + h * 8) * HW);
        }
        CP_COMMIT();
    }

    for (int kt = 0; kt < 16; kt++) {
        const int buf = kt & 3;
        CP_WAIT2();
        __syncthreads();

        if (kt < 13) {
            const int s = kt + 3, nb = s & 3;
#pragma unroll
            for (int h = 0; h < 2; h++) {
                cpa16(sbase + (SA_OFF(nb, lrow + h * 8) + lcol) * 4,
                      gA + (size_t)(s * 16 + h * 8) * wstride);
                cpa16(sbase + (SB_OFF(nb, lrow + h * 8) + lcol) * 4,
                      gB + (size_t)(s * 16 + h * 8) * HW);
            }
        }
        CP_COMMIT();

        const uint32_t* A0 = dsm + SA_OFF(buf, 0) + (lane & 3) * SSTRIDE
                                 + mw * 64 + (lane >> 2);
        const uint32_t* B0 = dsm + SB_OFF(buf, 0) + (lane & 3) * SSTRIDE
                                 + nw * 32 + (lane >> 2);
#pragma unroll
        for (int kk = 0; kk < 16; kk += 8) {
            const uint32_t* Ak = A0 + kk * SSTRIDE;
            const uint32_t* Bk = B0 + kk * SSTRIDE;
            uint32_t af[4][4];
#pragma unroll
            for (int mi = 0; mi < 4; mi++) {
                af[mi][0] = Ak[mi * 16];
                af[mi][1] = Ak[mi * 16 + 8];
                af[mi][2] = Ak[4 * SSTRIDE + mi * 16];
                af[mi][3] = Ak[4 * SSTRIDE + mi * 16 + 8];
            }
            uint32_t bfr[4][2];
#pragma unroll
            for (int nj = 0; nj < 4; nj++) {
                bfr[nj][0] = Bk[nj * 8];
                bfr[nj][1] = Bk[4 * SSTRIDE + nj * 8];
            }
#pragma unroll
            for (int mi = 0; mi < 4; mi++)
#pragma unroll
                for (int nj = 0; nj < 4; nj++)
                    mma_tf32(acc[mi][nj], af[mi], bfr[nj]);
        }
        __syncthreads();
    }

#pragma unroll
    for (int mi = 0; mi < 4; mi++) {
        int mr0 = m0 + mw * 64 + mi * 16 + (lane >> 2);
        float bv0 = bias[mr0];
        float bv1 = bias[mr0 + 8];
        float* y0 = Y + ((size_t)(mr0 >> 8) * BATCH + b) * CHW + (size_t)(mr0 & 255) * HW + n0;
        int mr1 = mr0 + 8;
        float* y1 = Y + ((size_t)(mr1 >> 8) * BATCH + b) * CHW + (size_t)(mr1 & 255) * HW + n0;
#pragma unroll
        for (int nj = 0; nj < 4; nj++) {
            int nc = nw * 32 + nj * 8 + 2 * (lane & 3);
            float2 v0 = make_float2(acc[mi][nj][0] + bv0, acc[mi][nj][1] + bv0);
            float2 v1 = make_float2(acc[mi][nj][2] + bv1, acc[mi][nj][3] + bv1);
            *(float2*)(y0 + nc) = v0;
            *(float2*)(y1 + nc) = v1;
        }
    }
}

// ---------------------------------------------------------------------------
// Fused attention, one CTA per (b,c):
//   GEMM1 (scores) in exact fp32 FFMA -> register softmax ->
//   GEMM2 (O = Hm @ A) on tf32 HMMA, computed as O^T (m=v, n=h, k=w) so no
//   smem transposes are needed:
//     A-operand: attn[w][v] in sG (stride 72 -> frag bank = 8k+n, conflict-free)
//     B-operand: Hm[h][w] natural layout in sF (stride 68 -> bank = lane, c-free)
// ---------------------------------------------------------------------------
__global__ __launch_bounds__(256)
void attn_kernel(const float* __restrict__ y, float* __restrict__ o) {
    const int bc = blockIdx.x;
    const size_t BCHW = (size_t)BATCH * CHW;
    const float* F  = y + (size_t)bc * HW;
    const float* G  = y + BCHW + (size_t)bc * HW;
    const float* Hm = y + 2 * BCHW + (size_t)bc * HW;

    __shared__ __align__(16) float sF[64][68];   // F, then Hm (tf32)
    __shared__ __align__(16) float sG[64][72];   // G, then attn (tf32)

    const int tid  = threadIdx.x;
    const int lane = tid & 31;
    const int warp = tid >> 5;
    const int tx   = tid & 15;
    const int ty   = tid >> 4;

    for (int i = tid * 4; i < 4096; i += 1024) {
        *(float4*)&sF[i >> 6][i & 63] = *(const float4*)&F[i];
        *(float4*)&sG[i >> 6][i & 63] = *(const float4*)&G[i];
    }
    __syncthreads();

    // GEMM1 (fp32): S[w][v] = sum_h F[h][w] G[h][v]; thread owns 4x4 at (ty*4, tx*4)
    float acc[4][4];
#pragma unroll
    for (int i = 0; i < 4; i++)
#pragma unroll
        for (int j = 0; j < 4; j++) acc[i][j] = 0.f;

#pragma unroll 4
    for (int h = 0; h < 64; h++) {
        float4 a4 = *(const float4*)&sF[h][ty * 4];
        float4 b4 = *(const float4*)&sG[h][tx * 4];
        float a[4] = {a4.x, a4.y, a4.z, a4.w};
        float bb[4] = {b4.x, b4.y, b4.z, b4.w};
#pragma unroll
        for (int i = 0; i < 4; i++)
#pragma unroll
            for (int j = 0; j < 4; j++) acc[i][j] = fmaf(a[i], bb[j], acc[i][j]);
    }

    // register softmax over v (rows spread across 16-lane groups)
#pragma unroll
    for (int i = 0; i < 4; i++) {
        float m = fmaxf(fmaxf(acc[i][0], acc[i][1]), fmaxf(acc[i][2], acc[i][3]));
#pragma unroll
        for (int s = 1; s < 16; s <<= 1)
            m = fmaxf(m, __shfl_xor_sync(0xffffffffu, m, s));
        float sum = 0.f;
#pragma unroll
        for (int j = 0; j < 4; j++) {
            acc[i][j] = __expf(acc[i][j] - m);
            sum += acc[i][j];
        }
#pragma unroll
        for (int s = 1; s < 16; s <<= 1)
            sum += __shfl_xor_sync(0xffffffffu, sum, s);
        float inv = 1.0f / sum;
#pragma unroll
        for (int j = 0; j < 4; j++) acc[i][j] *= inv;
    }

    __syncthreads();   // done reading F/G

    // stage tf32 attn into sG[w][v], tf32 Hm into sF[h][w] (natural layout)
#pragma unroll
    for (int i = 0; i < 4; i++)
#pragma unroll
        for (int j = 0; j < 4; j++) sG[ty * 4 + i][tx * 4 + j] = rtf(acc[i][j]);
    for (int i = tid * 4; i < 4096; i += 1024) {
        float4 v = *(const float4*)&Hm[i];
        v.x = rtf(v.x); v.y = rtf(v.y); v.z = rtf(v.z); v.w = rtf(v.w);
        *(float4*)&sF[i >> 6][i & 63] = v;
    }
    __syncthreads();

    // GEMM2 (tf32 HMMA): C[v][h] = sum_w attn[w][v] * Hm[h][w]  (= O^T)
    // warp: m-tile mt = warp>>1 (v), n-tiles (warp&1)*4 .. +3 (h)
    const int mt = warp >> 1;
    const int nb = (warp & 1) * 4;
    float c2[4][4];
#pragma unroll
    for (int nj = 0; nj < 4; nj++)
#pragma unroll
        for (int r = 0; r < 4; r++) c2[nj][r] = 0.f;

#pragma unroll
    for (int k0 = 0; k0 < 64; k0 += 8) {
        uint32_t af[4];
        {
            const int v0 = mt * 16 + (lane >> 2);
            const int w0 = k0 + (lane & 3);
            af[0] = __float_as_uint(sG[w0][v0]);
            af[1] = __float_as_uint(sG[w0][v0 + 8]);
            af[2] = __float_as_uint(sG[w0 + 4][v0]);
            af[3] = __float_as_uint(sG[w0 + 4][v0 + 8]);
        }
#pragma unroll
        for (int nj = 0; nj < 4; nj++) {
            const int h0 = (nb + nj) * 8 + (lane >> 2);
            const int w0 = k0 + (lane & 3);
            uint32_t bfr[2];
            bfr[0] = __float_as_uint(sF[h0][w0]);
            bfr[1] = __float_as_uint(sF[h0][w0 + 4]);
            mma_tf32(c2[nj], af, bfr);
        }
    }

    // store O[h][v] from C[v][h] fragments, tf32-rounded for the final conv
    float* O = o + (size_t)bc * HW;
    const int vr = mt * 16 + (lane >> 2);
#pragma unroll
    for (int nj = 0; nj < 4; nj++) {
        const int hc = (nb + nj) * 8 + 2 * (lane & 3);
        O[hc * 64 + vr]           = rtf(c2[nj][0]);
        O[(hc + 1) * 64 + vr]     = rtf(c2[nj][1]);
        O[hc * 64 + vr + 8]       = rtf(c2[nj][2]);
        O[(hc + 1) * 64 + vr + 8] = rtf(c2[nj][3]);
    }
}

// ---------------------------------------------------------------------------
extern "C" void kernel_launch(void* const* d_in, const int* in_sizes, int n_in,
                              void* d_out, int out_size) {
    const float* x  = (const float*)d_in[0];
    const float* wf = (const float*)d_in[1];
    const float* bf = (const float*)d_in[2];
    const float* wg = (const float*)d_in[3];
    const float* bg = (const float*)d_in[4];
    const float* wh = (const float*)d_in[5];
    const float* bh = (const float*)d_in[6];
    const float* wv = (const float*)d_in[7];
    const float* bv = (const float*)d_in[8];

    float *yb, *ob, *xr, *wt, *wtv, *bcat;
    cudaGetSymbolAddress((void**)&yb,   g_y);
    cudaGetSymbolAddress((void**)&ob,   g_o);
    cudaGetSymbolAddress((void**)&xr,   g_xr);
    cudaGetSymbolAddress((void**)&wt,   g_wt);
    cudaGetSymbolAddress((void**)&wtv,  g_wtv);
    cudaGetSymbolAddress((void**)&bcat, g_bcat);

    cudaFuncSetAttribute(conv_hmma_kernel,
                         cudaFuncAttributeMaxDynamicSharedMemorySize, CONV_SMEM);

    // 1) weight transpose + rounding; x rounding
    prep_kernel<<<768, 256>>>(wf, wg, wh, wv, bf, bg, bh);
    round_x_kernel<<<16384, 256>>>(x);

    // 2) fused f/g/h conv: M=768 (6 tiles), N=4096 (32 tiles), B=16
    conv_hmma_kernel<<<dim3(32, 6, 16), 256, CONV_SMEM>>>(xr, wt, bcat, yb, 768);

    // 3) per-(b,c) attention
    attn_kernel<<<4096, 256>>>(yb, ob);

    // 4) output conv: M=256 (2 tiles)
    conv_hmma_kernel<<<dim3(32, 2, 16), 256, CONV_SMEM>>>(ob, wtv, bv, (float*)d_out, 256);
}